// round 3
// baseline (speedup 1.0000x reference)
#include <cuda_runtime.h>
#include <cstddef>

// Problem constants
#define LL      512
#define BB      8
#define ND      1024
#define NE      1024
#define NV      32000
#define NPROJ   512
#define MT      (LL * BB)          // 4096 rows
#define OUT_MAIN ((size_t)MT * NV) // 131,072,000 floats

// Scratch (device globals; no allocations allowed)
__device__ float g_hA[(size_t)MT * ND];       // 16 MB
__device__ float g_hB[(size_t)MT * ND];       // 16 MB
__device__ float g_U [(size_t)MT * 4 * ND];   // 64 MB (max width 4096)
__device__ float g_T [(size_t)MT * NPROJ];    // 8 MB

// ---------------------------------------------------------------------------
// Embedding gather: h[m, :] = emb[x[m], :]
// ---------------------------------------------------------------------------
__global__ void embed_kernel(const float* __restrict__ emb,
                             const int*   __restrict__ x,
                             float*       __restrict__ h) {
    int m   = blockIdx.x;          // 0..4095
    int tok = x[m];
    const float4* src = reinterpret_cast<const float4*>(emb + (size_t)tok * NE);
    float4*       dst = reinterpret_cast<float4*>(h + (size_t)m * NE);
    dst[threadIdx.x] = src[threadIdx.x];   // 256 threads x float4 = 1024 floats
}

// ---------------------------------------------------------------------------
// SGEMM: C[M,N] = A[M,K] @ B[K,N] (+ bias). Row-major. Dims are exact
// multiples of 128 (M,N) and 8 (K) for this problem -> no bounds checks.
// 128x128 block, BK=8, 8x8 per thread, 256 threads.
// ---------------------------------------------------------------------------
template<bool HAS_BIAS>
__global__ void __launch_bounds__(256)
sgemm_kernel(const float* __restrict__ A,
             const float* __restrict__ B,
             const float* __restrict__ bias,
             float*       __restrict__ C,
             int M, int N, int K) {
    __shared__ float As[8][128];
    __shared__ float Bs[8][128];

    const int tid = threadIdx.x;
    const int bx  = blockIdx.x;   // along N
    const int by  = blockIdx.y;   // along M

    const float* Ab = A + (size_t)by * 128 * K;
    const float* Bb = B + (size_t)bx * 128;
    float*       Cb = C + (size_t)by * 128 * N + (size_t)bx * 128;

    const int aRow = tid >> 1;          // 0..127
    const int aCol = (tid & 1) << 2;    // 0 or 4
    const int bRow = tid >> 5;          // 0..7
    const int bCol = (tid & 31) << 2;   // 0..124

    const int tr = (tid >> 4) << 3;     // 0..120 step 8
    const int tc = (tid & 15) << 3;     // 0..120 step 8

    float acc[8][8];
    #pragma unroll
    for (int i = 0; i < 8; i++)
        #pragma unroll
        for (int j = 0; j < 8; j++)
            acc[i][j] = 0.0f;

    for (int k0 = 0; k0 < K; k0 += 8) {
        float4 a4 = *reinterpret_cast<const float4*>(Ab + (size_t)aRow * K + k0 + aCol);
        As[aCol + 0][aRow] = a4.x;
        As[aCol + 1][aRow] = a4.y;
        As[aCol + 2][aRow] = a4.z;
        As[aCol + 3][aRow] = a4.w;
        *reinterpret_cast<float4*>(&Bs[bRow][bCol]) =
            *reinterpret_cast<const float4*>(Bb + (size_t)(k0 + bRow) * N + bCol);
        __syncthreads();

        #pragma unroll
        for (int k = 0; k < 8; k++) {
            float ar[8], br[8];
            #pragma unroll
            for (int i = 0; i < 8; i++) ar[i] = As[k][tr + i];
            #pragma unroll
            for (int j = 0; j < 8; j++) br[j] = Bs[k][tc + j];
            #pragma unroll
            for (int i = 0; i < 8; i++)
                #pragma unroll
                for (int j = 0; j < 8; j++)
                    acc[i][j] += ar[i] * br[j];
        }
        __syncthreads();
    }

    #pragma unroll
    for (int i = 0; i < 8; i++) {
        #pragma unroll
        for (int j = 0; j < 8; j += 4) {
            float4 o;
            o.x = acc[i][j + 0];
            o.y = acc[i][j + 1];
            o.z = acc[i][j + 2];
            o.w = acc[i][j + 3];
            if (HAS_BIAS) {
                int nb = bx * 128 + tc + j;
                o.x += bias[nb + 0];
                o.y += bias[nb + 1];
                o.z += bias[nb + 2];
                o.w += bias[nb + 3];
            }
            *reinterpret_cast<float4*>(Cb + (size_t)(tr + i) * N + tc + j) = o;
        }
    }
}

// ---------------------------------------------------------------------------
// SRU scan: 8192 independent (b,d) chains over L=512 steps.
//   f = sigmoid(u1 + vf*c + bf); c = (c-u0)*f + u0
//   r = sigmoid(u2 + vr*c + br); h = (c-res)*r + res
// ---------------------------------------------------------------------------
__device__ __forceinline__ float sigmoidf_(float z) {
    return 1.0f / (1.0f + __expf(-z));
}

__global__ void __launch_bounds__(128)
scan_kernel(const float* __restrict__ U,   int uStride,
            const float* __restrict__ res, int resStride,
            const float* __restrict__ v,
            const float* __restrict__ bb,
            const float* __restrict__ c0,
            float*       __restrict__ hout,
            float*       __restrict__ cT) {
    int idx = blockIdx.x * blockDim.x + threadIdx.x;  // 0..8191
    int b   = idx >> 10;   // 0..7
    int d   = idx & 1023;

    float c  = c0[idx];
    float vf = v[d],      vr = v[ND + d];
    float bf = bb[d],     br = bb[ND + d];

    const float* Up = U   + (size_t)b * uStride   + d;
    const float* Rp = res + (size_t)b * resStride + d;
    float*       Hp = hout + (size_t)b * ND + d;

    const size_t uStep = (size_t)BB * uStride;
    const size_t rStep = (size_t)BB * resStride;

    for (int t = 0; t < LL; t++) {
        float u0 = Up[0];
        float u1 = Up[ND];
        float u2 = Up[2 * ND];
        float rt = Rp[0];

        float f = sigmoidf_(u1 + vf * c + bf);
        c = (c - u0) * f + u0;
        float r = sigmoidf_(u2 + vr * c + br);
        Hp[0] = (c - rt) * r + rt;

        Up += uStep;
        Rp += rStep;
        Hp += (size_t)BB * ND;
    }
    cT[idx] = c;
}

// ---------------------------------------------------------------------------
// Launch
// ---------------------------------------------------------------------------
extern "C" void kernel_launch(void* const* d_in, const int* in_sizes, int n_in,
                              void* d_out, int out_size) {
    const float* emb    = (const float*)d_in[0];   // (32000,1024)
    const float* W0     = (const float*)d_in[1];   // (1024,4096)
    const float* P1     = (const float*)d_in[2];   // (3,1024,512)
    const float* P2     = (const float*)d_in[3];   // (3,512,3072)
    const float* v      = (const float*)d_in[4];   // (4,2048)
    const float* bvec   = (const float*)d_in[5];   // (4,2048)
    const float* outW   = (const float*)d_in[6];   // (1024,32000)
    const float* outb   = (const float*)d_in[7];   // (32000,)
    const float* hidden = (const float*)d_in[8];   // (4,8,1024)
    const int*   x      = (const int*)d_in[9];     // (512,8)

    float* out = (float*)d_out;
    float* cs  = out + OUT_MAIN;                   // (4,8,1024)

    float *hA, *hB, *U, *T;
    cudaGetSymbolAddress((void**)&hA, g_hA);
    cudaGetSymbolAddress((void**)&hB, g_hB);
    cudaGetSymbolAddress((void**)&U,  g_U);
    cudaGetSymbolAddress((void**)&T,  g_T);

    // 1) Embedding gather -> hA
    embed_kernel<<<MT, 256>>>(emb, x, hA);

    // 2) Layer 0: U4 = hA @ W0  (4096 x 4096, K=1024)
    sgemm_kernel<false><<<dim3(4 * ND / 128, MT / 128), 256>>>(hA, W0, nullptr, U, MT, 4 * ND, NE);
    //    scan: res lives inside U at column offset 3*ND; h -> hB
    scan_kernel<<<64, 128>>>(U, 4 * ND, U + 3 * ND, 4 * ND,
                             v, bvec, hidden, hB, cs);

    // 3) Layers 1..3: T = h @ P1[i]; U3 = T @ P2[i]; scan with res = h
    float* hin  = hB;
    float* hout = hA;
    for (int i = 0; i < 3; i++) {
        sgemm_kernel<false><<<dim3(NPROJ / 128, MT / 128), 256>>>(
            hin, P1 + (size_t)i * ND * NPROJ, nullptr, T, MT, NPROJ, ND);
        sgemm_kernel<false><<<dim3(3 * ND / 128, MT / 128), 256>>>(
            T, P2 + (size_t)i * NPROJ * 3 * ND, nullptr, U, MT, 3 * ND, NPROJ);
        scan_kernel<<<64, 128>>>(U, 3 * ND, hin, ND,
                                 v + (size_t)(i + 1) * 2 * ND,
                                 bvec + (size_t)(i + 1) * 2 * ND,
                                 hidden + (size_t)(i + 1) * BB * ND,
                                 hout, cs + (size_t)(i + 1) * BB * ND);
        float* tmp = hin; hin = hout; hout = tmp;
    }

    // 4) Output projection: out = h @ outW + outb  (4096 x 32000, K=1024)
    sgemm_kernel<true><<<dim3(NV / 128, MT / 128), 256>>>(hin, outW, outb, out, MT, NV, NE);
}

// round 4
// speedup vs baseline: 2.2484x; 2.2484x over previous
#include <cuda_runtime.h>
#include <cstdint>
#include <cstddef>

// Problem constants
#define LL      512
#define BB      8
#define ND      1024
#define NE      1024
#define NV      32000
#define NPROJ   512
#define MT      (LL * BB)          // 4096 rows
#define OUT_MAIN ((size_t)MT * NV)

// GEMM tiling
#define BM 128
#define BN 128
#define BK 32
#define SA 36    // A_s row stride in elements (pad 32 -> 36: conflict-free frag loads)
#define SB 136   // B_s row stride in elements (pad 128 -> 136)
#define SMEM_BYTES ((BM * SA + BK * SB) * 2 * 4)   // 71680

// ---------------------------------------------------------------------------
// Scratch (device globals; allocations are forbidden)
// ---------------------------------------------------------------------------
__device__ float    g_hA[(size_t)MT * ND];          // 16 MB  (fp32 activations)
__device__ float    g_hB[(size_t)MT * ND];          // 16 MB
__device__ float    g_U [(size_t)MT * 4 * ND];      // 64 MB
__device__ float    g_T [(size_t)MT * NPROJ];       //  8 MB
__device__ uint32_t g_At [(size_t)MT * ND];         // 16 MB  (tf32 A operand)
__device__ uint32_t g_Tt [(size_t)MT * NPROJ];      //  8 MB
__device__ uint32_t g_W0t[(size_t)NE * 4 * ND];     // 16 MB  (tf32 weights)
__device__ uint32_t g_P1t[(size_t)3 * ND * NPROJ];  //  6 MB
__device__ uint32_t g_P2t[(size_t)3 * NPROJ * 3 * ND]; // 18 MB
__device__ uint32_t g_oWt[(size_t)ND * NV];         // 128 MB

// ---------------------------------------------------------------------------
// Helpers
// ---------------------------------------------------------------------------
__device__ __forceinline__ uint32_t f2tf32(float x) {
    uint32_t r;
    asm("cvt.rna.tf32.f32 %0, %1;" : "=r"(r) : "f"(x));
    return r;
}

__device__ __forceinline__ void cp_async16(uint32_t saddr, const void* gptr) {
    asm volatile("cp.async.ca.shared.global [%0], [%1], 16;\n" :: "r"(saddr), "l"(gptr));
}
__device__ __forceinline__ void cp_commit() {
    asm volatile("cp.async.commit_group;\n");
}
template<int N>
__device__ __forceinline__ void cp_wait() {
    asm volatile("cp.async.wait_group %0;\n" :: "n"(N));
}

// ---------------------------------------------------------------------------
// Elementwise fp32 -> tf32 (round-to-nearest) conversion, float4 vectorized
// ---------------------------------------------------------------------------
__global__ void __launch_bounds__(256)
cvt_tf32_kernel(const float4* __restrict__ in, uint4* __restrict__ out, int n4) {
    int i = blockIdx.x * blockDim.x + threadIdx.x;
    if (i < n4) {
        float4 v = in[i];
        uint4 o;
        o.x = f2tf32(v.x); o.y = f2tf32(v.y);
        o.z = f2tf32(v.z); o.w = f2tf32(v.w);
        out[i] = o;
    }
}

// ---------------------------------------------------------------------------
// Embedding gather fused with tf32 conversion: At[m,:] = tf32(emb[x[m],:])
// ---------------------------------------------------------------------------
__global__ void embed_cvt_kernel(const float* __restrict__ emb,
                                 const int*   __restrict__ x,
                                 uint32_t*    __restrict__ At) {
    int m   = blockIdx.x;
    int tok = x[m];
    const float4* src = reinterpret_cast<const float4*>(emb + (size_t)tok * NE);
    uint4*        dst = reinterpret_cast<uint4*>(At + (size_t)m * NE);
    float4 v = src[threadIdx.x];
    uint4 o;
    o.x = f2tf32(v.x); o.y = f2tf32(v.y);
    o.z = f2tf32(v.z); o.w = f2tf32(v.w);
    dst[threadIdx.x] = o;
}

// ---------------------------------------------------------------------------
// TF32 tensor-core GEMM: C[M,N] = A[M,K] @ B[K,N] (+ bias)
// A, B are pre-rounded tf32 bit patterns (uint32). C is fp32.
// Block 128x128x32, 8 warps (2x4), warp tile 64x32, mma.m16n8k8.
// All dims: M%128==0, N%128==0, K%32==0 (holds for every call here).
// ---------------------------------------------------------------------------
template<bool HAS_BIAS>
__global__ void __launch_bounds__(256)
gemm_tf32_kernel(const uint32_t* __restrict__ A,
                 const uint32_t* __restrict__ B,
                 const float*    __restrict__ bias,
                 float*          __restrict__ C,
                 int M, int N, int K) {
    extern __shared__ uint32_t smem[];
    uint32_t* As = smem;                    // [2][BM*SA]
    uint32_t* Bs = smem + 2 * BM * SA;      // [2][BK*SB]

    const int tid  = threadIdx.x;
    const int wid  = tid >> 5;
    const int lane = tid & 31;
    const int g    = lane >> 2;     // 0..7
    const int t4   = lane & 3;      // 0..3
    const int wm   = wid >> 2;      // 0..1  (M direction)
    const int wn   = wid & 3;       // 0..3  (N direction)

    const int bm = blockIdx.y * BM;
    const int bn = blockIdx.x * BN;

    // cp.async source/dest mapping
    const int aRow = tid >> 1;              // 0..127
    const int aCol = (tid & 1) << 4;        // 0 or 16
    const int bRow = tid >> 3;              // 0..31
    const int bCol = (tid & 7) << 4;        // 0..112

    const uint32_t* Ag = A + (size_t)(bm + aRow) * K + aCol;
    const uint32_t* Bg = B + (size_t)bRow * N + bn + bCol;

    uint32_t asBase = (uint32_t)__cvta_generic_to_shared(As) + (aRow * SA + aCol) * 4;
    uint32_t bsBase = (uint32_t)__cvta_generic_to_shared(Bs) + (bRow * SB + bCol) * 4;

    float acc[4][4][4];
    #pragma unroll
    for (int i = 0; i < 4; i++)
        #pragma unroll
        for (int j = 0; j < 4; j++)
            #pragma unroll
            for (int r = 0; r < 4; r++)
                acc[i][j][r] = 0.0f;

    const int NT = K / BK;

    // Prologue: stage 0
    {
        #pragma unroll
        for (int i = 0; i < 4; i++)
            cp_async16(asBase + i * 16, Ag + i * 4);
        #pragma unroll
        for (int i = 0; i < 4; i++)
            cp_async16(bsBase + i * 16, Bg + i * 4);
        cp_commit();
    }

    for (int kt = 0; kt < NT; kt++) {
        if (kt + 1 < NT) {
            int s = (kt + 1) & 1;
            const uint32_t* Agk = Ag + (kt + 1) * BK;
            const uint32_t* Bgk = Bg + (size_t)(kt + 1) * BK * N;
            uint32_t asS = asBase + s * BM * SA * 4;
            uint32_t bsS = bsBase + s * BK * SB * 4;
            #pragma unroll
            for (int i = 0; i < 4; i++)
                cp_async16(asS + i * 16, Agk + i * 4);
            #pragma unroll
            for (int i = 0; i < 4; i++)
                cp_async16(bsS + i * 16, Bgk + i * 4);
            cp_commit();
            cp_wait<1>();
        } else {
            cp_wait<0>();
        }
        __syncthreads();

        const uint32_t* Asl = As + (kt & 1) * BM * SA;
        const uint32_t* Bsl = Bs + (kt & 1) * BK * SB;

        #pragma unroll
        for (int kk = 0; kk < 4; kk++) {
            uint32_t af[4][4];
            uint32_t bf[4][2];
            #pragma unroll
            for (int mi = 0; mi < 4; mi++) {
                const uint32_t* p = Asl + (size_t)(wm * 64 + mi * 16 + g) * SA + kk * 8 + t4;
                af[mi][0] = p[0];
                af[mi][1] = p[8 * SA];
                af[mi][2] = p[4];
                af[mi][3] = p[8 * SA + 4];
            }
            #pragma unroll
            for (int ni = 0; ni < 4; ni++) {
                const uint32_t* p = Bsl + (size_t)(kk * 8 + t4) * SB + wn * 32 + ni * 8 + g;
                bf[ni][0] = p[0];
                bf[ni][1] = p[4 * SB];
            }
            #pragma unroll
            for (int mi = 0; mi < 4; mi++)
                #pragma unroll
                for (int ni = 0; ni < 4; ni++) {
                    asm volatile(
                        "mma.sync.aligned.m16n8k8.row.col.f32.tf32.tf32.f32 "
                        "{%0,%1,%2,%3}, {%4,%5,%6,%7}, {%8,%9}, {%0,%1,%2,%3};\n"
                        : "+f"(acc[mi][ni][0]), "+f"(acc[mi][ni][1]),
                          "+f"(acc[mi][ni][2]), "+f"(acc[mi][ni][3])
                        : "r"(af[mi][0]), "r"(af[mi][1]), "r"(af[mi][2]), "r"(af[mi][3]),
                          "r"(bf[ni][0]), "r"(bf[ni][1]));
                }
        }
        __syncthreads();
    }

    // Epilogue
    #pragma unroll
    for (int mi = 0; mi < 4; mi++) {
        #pragma unroll
        for (int ni = 0; ni < 4; ni++) {
            int col = bn + wn * 32 + ni * 8 + 2 * t4;
            float bx = 0.0f, by = 0.0f;
            if (HAS_BIAS) { bx = bias[col]; by = bias[col + 1]; }
            float* c0 = C + (size_t)(bm + wm * 64 + mi * 16 + g) * N + col;
            float2 v0; v0.x = acc[mi][ni][0] + bx; v0.y = acc[mi][ni][1] + by;
            float2 v1; v1.x = acc[mi][ni][2] + bx; v1.y = acc[mi][ni][3] + by;
            *reinterpret_cast<float2*>(c0)         = v0;
            *reinterpret_cast<float2*>(c0 + 8 * N) = v1;
        }
    }
}

// ---------------------------------------------------------------------------
// SRU scan: 8192 independent (b,d) chains over L=512 steps
// ---------------------------------------------------------------------------
__device__ __forceinline__ float sigmoidf_(float z) {
    return 1.0f / (1.0f + __expf(-z));
}

__global__ void __launch_bounds__(128)
scan_kernel(const float* __restrict__ U,   int uStride,
            const float* __restrict__ res, int resStride,
            const float* __restrict__ v,
            const float* __restrict__ bb,
            const float* __restrict__ c0,
            float*       __restrict__ hout,
            float*       __restrict__ cT) {
    int idx = blockIdx.x * blockDim.x + threadIdx.x;  // 0..8191
    int b   = idx >> 10;
    int d   = idx & 1023;

    float c  = c0[idx];
    float vf = v[d],  vr = v[ND + d];
    float bf = bb[d], br = bb[ND + d];

    const float* Up = U    + (size_t)b * uStride   + d;
    const float* Rp = res  + (size_t)b * resStride + d;
    float*       Hp = hout + (size_t)b * ND + d;

    const size_t uStep = (size_t)BB * uStride;
    const size_t rStep = (size_t)BB * resStride;

    for (int t = 0; t < LL; t++) {
        float u0 = Up[0];
        float u1 = Up[ND];
        float u2 = Up[2 * ND];
        float rt = Rp[0];

        float f = sigmoidf_(u1 + vf * c + bf);
        c = (c - u0) * f + u0;
        float r = sigmoidf_(u2 + vr * c + br);
        Hp[0] = (c - rt) * r + rt;

        Up += uStep;
        Rp += rStep;
        Hp += (size_t)BB * ND;
    }
    cT[idx] = c;
}

// ---------------------------------------------------------------------------
// Launch
// ---------------------------------------------------------------------------
static inline void launch_cvt(const float* src, uint32_t* dst, size_t n) {
    int n4 = (int)(n / 4);
    cvt_tf32_kernel<<<(n4 + 255) / 256, 256>>>(
        reinterpret_cast<const float4*>(src), reinterpret_cast<uint4*>(dst), n4);
}

extern "C" void kernel_launch(void* const* d_in, const int* in_sizes, int n_in,
                              void* d_out, int out_size) {
    const float* emb    = (const float*)d_in[0];   // (32000,1024)
    const float* W0     = (const float*)d_in[1];   // (1024,4096)
    const float* P1     = (const float*)d_in[2];   // (3,1024,512)
    const float* P2     = (const float*)d_in[3];   // (3,512,3072)
    const float* v      = (const float*)d_in[4];   // (4,2048)
    const float* bvec   = (const float*)d_in[5];   // (4,2048)
    const float* outW   = (const float*)d_in[6];   // (1024,32000)
    const float* outb   = (const float*)d_in[7];   // (32000,)
    const float* hidden = (const float*)d_in[8];   // (4,8,1024)
    const int*   x      = (const int*)d_in[9];     // (512,8)

    float* out = (float*)d_out;
    float* cs  = out + OUT_MAIN;

    float *hA, *hB, *U, *T;
    uint32_t *At, *Tt, *W0t, *P1t, *P2t, *oWt;
    cudaGetSymbolAddress((void**)&hA,  g_hA);
    cudaGetSymbolAddress((void**)&hB,  g_hB);
    cudaGetSymbolAddress((void**)&U,   g_U);
    cudaGetSymbolAddress((void**)&T,   g_T);
    cudaGetSymbolAddress((void**)&At,  g_At);
    cudaGetSymbolAddress((void**)&Tt,  g_Tt);
    cudaGetSymbolAddress((void**)&W0t, g_W0t);
    cudaGetSymbolAddress((void**)&P1t, g_P1t);
    cudaGetSymbolAddress((void**)&P2t, g_P2t);
    cudaGetSymbolAddress((void**)&oWt, g_oWt);

    cudaFuncSetAttribute(gemm_tf32_kernel<false>,
                         cudaFuncAttributeMaxDynamicSharedMemorySize, SMEM_BYTES);
    cudaFuncSetAttribute(gemm_tf32_kernel<true>,
                         cudaFuncAttributeMaxDynamicSharedMemorySize, SMEM_BYTES);

    // 0) Weight conversions to tf32 (every launch; deterministic)
    launch_cvt(W0,  W0t, (size_t)NE * 4 * ND);
    launch_cvt(P1,  P1t, (size_t)3 * ND * NPROJ);
    launch_cvt(P2,  P2t, (size_t)3 * NPROJ * 3 * ND);
    launch_cvt(outW, oWt, (size_t)ND * NV);

    // 1) Embedding gather (+tf32) -> At
    embed_cvt_kernel<<<MT, 256>>>(emb, x, At);

    // 2) Layer 0: U4 = h @ W0  (4096 x 4096, K=1024); residual = U[:,3d:]
    gemm_tf32_kernel<false><<<dim3(4 * ND / BN, MT / BM), 256, SMEM_BYTES>>>(
        At, W0t, nullptr, U, MT, 4 * ND, NE);
    scan_kernel<<<64, 128>>>(U, 4 * ND, U + 3 * ND, 4 * ND,
                             v, bvec, hidden, hB, cs);

    // 3) Layers 1..3
    float* hin  = hB;
    float* hout = hA;
    for (int i = 0; i < 3; i++) {
        launch_cvt(hin, At, (size_t)MT * ND);
        gemm_tf32_kernel<false><<<dim3(NPROJ / BN, MT / BM), 256, SMEM_BYTES>>>(
            At, P1t + (size_t)i * ND * NPROJ, nullptr, T, MT, NPROJ, ND);
        launch_cvt(T, Tt, (size_t)MT * NPROJ);
        gemm_tf32_kernel<false><<<dim3(3 * ND / BN, MT / BM), 256, SMEM_BYTES>>>(
            Tt, P2t + (size_t)i * NPROJ * 3 * ND, nullptr, U, MT, 3 * ND, NPROJ);
        scan_kernel<<<64, 128>>>(U, 3 * ND, hin, ND,
                                 v + (size_t)(i + 1) * 2 * ND,
                                 bvec + (size_t)(i + 1) * 2 * ND,
                                 hidden + (size_t)(i + 1) * BB * ND,
                                 hout, cs + (size_t)(i + 1) * BB * ND);
        float* tmp = hin; hin = hout; hout = tmp;
    }

    // 4) Output projection: out = h @ outW + outb  (4096 x 32000, K=1024)
    launch_cvt(hin, At, (size_t)MT * ND);
    gemm_tf32_kernel<true><<<dim3(NV / BN, MT / BM), 256, SMEM_BYTES>>>(
        At, oWt, outb, out, MT, NV, NE);
}